// round 14
// baseline (speedup 1.0000x reference)
#include <cuda_runtime.h>
#include <cstdint>

// snn_input: integrate-and-fire over T=32 steps, N=4194304 neurons.
//   per step: m += image[t]; spk = m >= 1.0f; m -= 1.0f if spk
// Output: [spikes (T*N, 0/1 float32), final mempot (N float32)].
//
// FINAL. 1.056 GB irreducible traffic, byte-exact at DRAM.
// dram__cycles_active ~83-84% is the binding resource; L2 ~39%,
// compute pipes idle. Full bracketed search:
//   TBATCH: 8 (~166) / 16 (best) / 32 (occ 11%, 174us)
//   access width: 128-bit best; 256-bit v8.f32 neutral
//   layout: lane-coalesced required (thread-consecutive -> L1 76%, 252us)
//   block: 256 (164.0) / 512 (163.6, best)
//   4x plateau runs: 163.6-164.1us, sigma < 1us
// Remaining gap to 8TB/s spec = DRAM-controller R/W-mix turnaround,
// unreachable from SASS (TMA shares the same path-independent ceiling).

static constexpr int TSTEPS = 32;
static constexpr int TBATCH = 16;
static constexpr float THRES = 1.0f;

__global__ __launch_bounds__(512) void snn_if_kernel(
    const float4* __restrict__ image,    // [T, N/4] as float4
    const float4* __restrict__ mempot0,  // [N/4]
    float4* __restrict__ out,            // [T*N/4 spikes][N/4 mempot]
    int n4)
{
    int i = blockIdx.x * blockDim.x + threadIdx.x;   // grid covers n4 exactly

    float4 m = __ldcs(&mempot0[i]);

#pragma unroll
    for (int tb = 0; tb < TSTEPS / TBATCH; tb++) {
        float4 im[TBATCH];
        // front-batched loads: 16 independent LDG.E.128.CS in flight
#pragma unroll
        for (int j = 0; j < TBATCH; j++) {
            im[j] = __ldcs(&image[(size_t)(tb * TBATCH + j) * n4 + i]);
        }
        // compute + store burst
#pragma unroll
        for (int j = 0; j < TBATCH; j++) {
            m.x += im[j].x; m.y += im[j].y; m.z += im[j].z; m.w += im[j].w;
            float4 s;
            s.x = (m.x >= THRES) ? 1.0f : 0.0f;
            s.y = (m.y >= THRES) ? 1.0f : 0.0f;
            s.z = (m.z >= THRES) ? 1.0f : 0.0f;
            s.w = (m.w >= THRES) ? 1.0f : 0.0f;
            // thres == 1.0 so subtracting s == subtracting s*THRES
            m.x -= s.x; m.y -= s.y; m.z -= s.z; m.w -= s.w;
            __stcs(&out[(size_t)(tb * TBATCH + j) * n4 + i], s);
        }
    }
    __stcs(&out[(size_t)TSTEPS * n4 + i], m);
}

extern "C" void kernel_launch(void* const* d_in, const int* in_sizes, int n_in,
                              void* d_out, int out_size)
{
    const float4* image   = (const float4*)d_in[0];
    const float4* mempot0 = (const float4*)d_in[1];
    float4*       out     = (float4*)d_out;

    int n  = in_sizes[1];      // 4194304 neurons
    int n4 = n / 4;            // 1048576 float4 lanes (= 2048 * 512 exactly)

    const int threads = 512;
    const int blocks  = n4 / threads;
    snn_if_kernel<<<blocks, threads>>>(image, mempot0, out, n4);
}